// round 1
// baseline (speedup 1.0000x reference)
#include <cuda_runtime.h>
#include <cstdint>

#define T     2048
#define E     512
#define HD    512
#define G4    2048   /* 4*HD */
#define TAGS  32
#define START 30
#define STOP  31
#define NEGV  (-10000.0f)

#define CANARY 0xFFFFFFFFu

// ---------------- scratch (device globals; no allocation) ----------------
__device__ float g_x[T * E];          // gathered embeddings          4 MB
__device__ float g_xg[2][T * G4];     // precomputed input gates     32 MB
__device__ float g_h[2][T * HD];      // LSTM hidden outputs          8 MB
__device__ float g_feats[T * TAGS];   // emissions                  256 KB

// ---------------- poison h buffer (data-as-flag sync) ----------------
__global__ void k_poison() {
    unsigned idx = (blockIdx.x * blockDim.x + threadIdx.x) * 4u;
    uint4 v = {CANARY, CANARY, CANARY, CANARY};
    *(uint4*)((unsigned*)g_h + idx) = v;
}

// ---------------- embedding gather ----------------
__global__ void k_gather(const int* __restrict__ sent, const float* __restrict__ emb) {
    int t = blockIdx.x;
    const float4* src = (const float4*)(emb + (size_t)sent[t] * E);
    ((float4*)(g_x + (size_t)t * E))[threadIdx.x] = src[threadIdx.x];
}

// ---------------- input GEMM: g_xg[d] = g_x @ W_ih[d]^T + b[d] ----------------
#define BM 128
#define BN 128
#define BK 16
__global__ void __launch_bounds__(256) k_gemm(const float* __restrict__ w_ih_f,
                                              const float* __restrict__ b_f,
                                              const float* __restrict__ w_ih_b,
                                              const float* __restrict__ b_b) {
    int d = blockIdx.z;
    const float* W    = d ? w_ih_b : w_ih_f;
    const float* bias = d ? b_b    : b_f;

    __shared__ float As[BK][BM];
    __shared__ float Bs[BK][BN];

    int tid = threadIdx.x;
    int tx = tid & 15, ty = tid >> 4;
    int t0 = blockIdx.y * BM, r0 = blockIdx.x * BN;

    float acc[8][8];
#pragma unroll
    for (int i = 0; i < 8; i++)
#pragma unroll
        for (int j = 0; j < 8; j++) acc[i][j] = 0.f;

    int lm = tid >> 2;            // 0..63
    int lk = (tid & 3) * 4;       // 0,4,8,12

    for (int k0 = 0; k0 < E; k0 += BK) {
#pragma unroll
        for (int rep = 0; rep < 2; rep++) {
            float4 v = *(const float4*)(g_x + (size_t)(t0 + lm + rep * 64) * E + k0 + lk);
            As[lk + 0][lm + rep * 64] = v.x;
            As[lk + 1][lm + rep * 64] = v.y;
            As[lk + 2][lm + rep * 64] = v.z;
            As[lk + 3][lm + rep * 64] = v.w;
            float4 w = *(const float4*)(W + (size_t)(r0 + lm + rep * 64) * E + k0 + lk);
            Bs[lk + 0][lm + rep * 64] = w.x;
            Bs[lk + 1][lm + rep * 64] = w.y;
            Bs[lk + 2][lm + rep * 64] = w.z;
            Bs[lk + 3][lm + rep * 64] = w.w;
        }
        __syncthreads();
#pragma unroll
        for (int k = 0; k < BK; k++) {
            float a[8], b[8];
            *(float4*)(a)     = *(const float4*)&As[k][ty * 8];
            *(float4*)(a + 4) = *(const float4*)&As[k][ty * 8 + 4];
            *(float4*)(b)     = *(const float4*)&Bs[k][tx * 8];
            *(float4*)(b + 4) = *(const float4*)&Bs[k][tx * 8 + 4];
#pragma unroll
            for (int i = 0; i < 8; i++)
#pragma unroll
                for (int j = 0; j < 8; j++) acc[i][j] += a[i] * b[j];
        }
        __syncthreads();
    }

    float* out = g_xg[d];
#pragma unroll
    for (int i = 0; i < 8; i++) {
        int t = t0 + ty * 8 + i;
#pragma unroll
        for (int j = 0; j < 8; j += 4) {
            int r = r0 + tx * 8 + j;
            float4 v = {acc[i][j] + bias[r], acc[i][j + 1] + bias[r + 1],
                        acc[i][j + 2] + bias[r + 2], acc[i][j + 3] + bias[r + 3]};
            *(float4*)(out + (size_t)t * G4 + r) = v;
        }
    }
}

// ---------------- persistent bidirectional LSTM recurrence ----------------
// 128 CTAs: CTA (d*64+b) owns h-indices [8b, 8b+8) of direction d.
// warp = column segment (64 cols), lane = local gate row (gate*8 + jj).
// W_hh rows live in registers. h broadcast through g_h with canary polling.
__device__ __forceinline__ float sig_f(float x) { return 1.f / (1.f + __expf(-x)); }
__device__ __forceinline__ float tanh_f(float x) { return 1.f - 2.f / (__expf(2.f * x) + 1.f); }

__global__ void __launch_bounds__(256, 1) k_lstm(const float* __restrict__ w_hh_f,
                                                 const float* __restrict__ w_hh_b,
                                                 const float* __restrict__ h0,
                                                 const float* __restrict__ c0) {
    int cta = blockIdx.x;
    int d = cta >> 6;
    int b = cta & 63;
    const float* Whh = d ? w_hh_b : w_hh_f;

    int tid  = threadIdx.x;
    int seg  = tid >> 5;            // warp id: which 64-col segment
    int lane = tid & 31;            // local row: gate*8 + jj
    int gate = lane >> 3, jj = lane & 7;
    int grow = gate * HD + b * 8 + jj;   // global gate row 0..2047

    // load this thread's weight segment into registers (one time)
    float w[64];
    {
        const float4* wr = (const float4*)(Whh + (size_t)grow * HD + seg * 64);
#pragma unroll
        for (int i = 0; i < 16; i++) {
            float4 v = wr[i];
            w[4 * i] = v.x; w[4 * i + 1] = v.y; w[4 * i + 2] = v.z; w[4 * i + 3] = v.w;
        }
    }

    __shared__ float sh_h[HD];
    __shared__ float sh_part[8 * 32];

    float c = 0.f;
    if (seg == 0 && lane < 8) c = c0[d * HD + b * 8 + lane];

    // prefetch xg for step 0 (warp0 only uses it)
    int t0i = d ? (T - 1) : 0;
    float xg_cur = 0.f;
    if (seg == 0) xg_cur = __ldg(&g_xg[d][(size_t)t0i * G4 + grow]);

    float* hout = g_h[d];

    for (int s = 0; s < T; s++) {
        int t = d ? (T - 1 - s) : s;

        if (s == 0) {
            float2 v = *(const float2*)(h0 + d * HD + tid * 2);
            sh_h[tid * 2]     = v.x;
            sh_h[tid * 2 + 1] = v.y;
        } else {
            int tp = d ? (t + 1) : (t - 1);
            volatile unsigned* hp = (volatile unsigned*)(hout + (size_t)tp * HD);
            unsigned a, bb;
            do { a  = hp[tid * 2];     } while (a  == CANARY);
            do { bb = hp[tid * 2 + 1]; } while (bb == CANARY);
            sh_h[tid * 2]     = __uint_as_float(a);
            sh_h[tid * 2 + 1] = __uint_as_float(bb);
        }
        __syncthreads();

        // per-thread partial dot over 64-col segment
        float sum = 0.f;
        const float4* h4 = (const float4*)(sh_h + seg * 64);
#pragma unroll
        for (int i = 0; i < 16; i++) {
            float4 v = h4[i];
            sum += w[4 * i] * v.x + w[4 * i + 1] * v.y + w[4 * i + 2] * v.z + w[4 * i + 3] * v.w;
        }
        sh_part[seg * 32 + lane] = sum;
        __syncthreads();

        if (seg == 0) {
            float xg_use = xg_cur;
            // prefetch next step's xg (issued early; ~1 full step to hide)
            if (s + 1 < T) {
                int tn = d ? (t - 1) : (t + 1);
                xg_cur = __ldg(&g_xg[d][(size_t)tn * G4 + grow]);
            }
            float tot = xg_use;
#pragma unroll
            for (int p = 0; p < 8; p++) tot += sh_part[p * 32 + lane];

            unsigned m = 0xFFFFFFFFu;
            float xi  = __shfl_sync(m, tot, (lane & 7));
            float xf  = __shfl_sync(m, tot, 8 + (lane & 7));
            float xgg = __shfl_sync(m, tot, 16 + (lane & 7));
            float xo  = __shfl_sync(m, tot, 24 + (lane & 7));
            if (lane < 8) {
                c = sig_f(xf) * c + sig_f(xi) * tanh_f(xgg);
                float hnew = sig_f(xo) * tanh_f(c);
                hout[(size_t)t * HD + b * 8 + lane] = hnew;   // publish (data IS the flag)
            }
        }
        // next iteration's barrier after sh_h fill provides the needed ordering
    }
}

// ---------------- emissions: feats = [hf|hb] @ W_out^T + b_out ----------------
__global__ void k_feats(const float* __restrict__ W_out, const float* __restrict__ b_out) {
    int t = blockIdx.x;
    int tid = threadIdx.x;         // 128
    int tag = tid >> 2, q = tid & 3;
    const float* wrow = W_out + (size_t)tag * 1024 + q * 256;
    const float* hs = (q < 2) ? (g_h[0] + (size_t)t * HD + q * 256)
                              : (g_h[1] + (size_t)t * HD + (q - 2) * 256);
    float sum = 0.f;
#pragma unroll 8
    for (int k = 0; k < 256; k += 4) {
        float4 w4 = *(const float4*)(wrow + k);
        float4 h4 = *(const float4*)(hs + k);
        sum += w4.x * h4.x + w4.y * h4.y + w4.z * h4.z + w4.w * h4.w;
    }
    sum += __shfl_xor_sync(0xFFFFFFFFu, sum, 1);
    sum += __shfl_xor_sync(0xFFFFFFFFu, sum, 2);
    if (q == 0) g_feats[t * TAGS + tag] = sum + b_out[tag];
}

// ---------------- Viterbi (single warp; bp in smem; exact argmax keys) --------
__device__ __forceinline__ unsigned long long vkey(float v, int j) {
    unsigned u = __float_as_uint(v);
    u ^= (u & 0x80000000u) ? 0xFFFFFFFFu : 0x80000000u;   // sortable float
    return (((unsigned long long)u) << 32) | (unsigned)(31 - j); // ties -> lowest j
}
__device__ __forceinline__ unsigned long long umax64(unsigned long long a, unsigned long long b) {
    return a > b ? a : b;
}

extern __shared__ unsigned char vit_smem[];
__global__ void k_viterbi(const float* __restrict__ transitions, float* __restrict__ out,
                          int out_size) {
    unsigned char* bp = vit_smem;                 // T*TAGS bytes
    float* fv = (float*)(vit_smem + T * TAGS);    // TAGS floats
    int n = threadIdx.x;

    float tr[TAGS];
#pragma unroll
    for (int j = 0; j < TAGS; j++) tr[j] = transitions[n * TAGS + j];

    fv[n] = (n == START) ? 0.f : NEGV;
    __syncwarp();

    float f0 = g_feats[0 * TAGS + n];
    float f1 = g_feats[1 * TAGS + n];

    for (int t = 0; t < T; t++) {
        unsigned long long k0 = 0, k1 = 0, k2 = 0, k3 = 0;
#pragma unroll
        for (int j = 0; j < 8; j++) {
            k0 = umax64(k0, vkey(fv[j]      + tr[j],      j));
            k1 = umax64(k1, vkey(fv[j + 8]  + tr[j + 8],  j + 8));
            k2 = umax64(k2, vkey(fv[j + 16] + tr[j + 16], j + 16));
            k3 = umax64(k3, vkey(fv[j + 24] + tr[j + 24], j + 24));
        }
        unsigned long long kmax = umax64(umax64(k0, k1), umax64(k2, k3));
        int arg = 31 - (int)(kmax & 31ull);
        float best = fv[arg] + tr[arg];
        float feat = (t & 1) ? f1 : f0;
        if (t + 2 < T) {
            float nf = g_feats[(t + 2) * TAGS + n];
            if (t & 1) f1 = nf; else f0 = nf;
        }
        float fvn = best + feat;
        bp[t * TAGS + n] = (unsigned char)arg;
        __syncwarp();
        fv[n] = fvn;
        __syncwarp();
    }

    // terminal argmax
    float term = fv[n] + transitions[STOP * TAGS + n];
    unsigned long long key = vkey(term, n);
#pragma unroll
    for (int o = 16; o; o >>= 1) key = umax64(key, __shfl_xor_sync(0xFFFFFFFFu, key, o));
    int best = 31 - (int)(key & 31ull);
    float score = fv[best] + transitions[STOP * TAGS + best];

    if (n == 0) {
        if (out_size >= T + 1) {
            out[0] = score;
            int tag = best;
            for (int t = T - 1; t >= 0; t--) {
                out[1 + t] = (float)tag;
                tag = bp[t * TAGS + tag];
            }
        } else if (out_size >= T) {
            int tag = best;
            for (int t = T - 1; t >= 0; t--) {
                out[t] = (float)tag;
                tag = bp[t * TAGS + tag];
            }
        } else {
            out[0] = score;
        }
    }
}

// ---------------- launch ----------------
extern "C" void kernel_launch(void* const* d_in, const int* in_sizes, int n_in,
                              void* d_out, int out_size) {
    const int*   sentence    = (const int*)d_in[0];
    const float* emb         = (const float*)d_in[1];
    const float* w_ih_f      = (const float*)d_in[2];
    const float* w_hh_f      = (const float*)d_in[3];
    const float* b_f         = (const float*)d_in[4];
    const float* w_ih_b      = (const float*)d_in[5];
    const float* w_hh_b      = (const float*)d_in[6];
    const float* b_b         = (const float*)d_in[7];
    const float* W_out       = (const float*)d_in[8];
    const float* b_out       = (const float*)d_in[9];
    const float* transitions = (const float*)d_in[10];
    const float* h0          = (const float*)d_in[11];
    const float* c0          = (const float*)d_in[12];
    float* out = (float*)d_out;

    // 2*T*HD uints / (256 threads * 4 per thread) = 2048 blocks
    k_poison<<<2048, 256>>>();
    k_gather<<<T, 128>>>(sentence, emb);
    k_gemm<<<dim3(16, 16, 2), 256>>>(w_ih_f, b_f, w_ih_b, b_b);
    k_lstm<<<128, 256>>>(w_hh_f, w_hh_b, h0, c0);
    k_feats<<<T, 128>>>(W_out, b_out);

    int vit_smem_bytes = T * TAGS + TAGS * (int)sizeof(float);
    cudaFuncSetAttribute(k_viterbi, cudaFuncAttributeMaxDynamicSharedMemorySize, vit_smem_bytes);
    k_viterbi<<<1, 32, vit_smem_bytes>>>(transitions, out, out_size);
}

// round 2
// speedup vs baseline: 1.2754x; 1.2754x over previous
#include <cuda_runtime.h>
#include <cstdint>

#define T     2048
#define E     512
#define HD    512
#define G4    2048   /* 4*HD */
#define TAGS  32
#define START 30
#define STOP  31
#define NEGV  (-10000.0f)

#define CANARY 0xFFFFFFFFu

// ---------------- scratch (device globals; no allocation) ----------------
__device__ float g_x[T * E];          // gathered embeddings          4 MB
__device__ float g_xg[2][T * G4];     // precomputed input gates     32 MB
__device__ float g_h[2][T * HD];      // LSTM hidden outputs          8 MB
__device__ float g_feats[T * TAGS];   // emissions                  256 KB

// ---------------- poison h buffer (data-as-flag sync) ----------------
__global__ void k_poison() {
    unsigned idx = (blockIdx.x * blockDim.x + threadIdx.x) * 4u;
    uint4 v = {CANARY, CANARY, CANARY, CANARY};
    *(uint4*)((unsigned*)g_h + idx) = v;
}

// ---------------- embedding gather ----------------
__global__ void k_gather(const int* __restrict__ sent, const float* __restrict__ emb) {
    int t = blockIdx.x;
    const float4* src = (const float4*)(emb + (size_t)sent[t] * E);
    ((float4*)(g_x + (size_t)t * E))[threadIdx.x] = src[threadIdx.x];
}

// ---------------- input GEMM: g_xg[d] = g_x @ W_ih[d]^T + b[d] ----------------
#define BM 128
#define BN 128
#define BK 16
__global__ void __launch_bounds__(256) k_gemm(const float* __restrict__ w_ih_f,
                                              const float* __restrict__ b_f,
                                              const float* __restrict__ w_ih_b,
                                              const float* __restrict__ b_b) {
    int d = blockIdx.z;
    const float* W    = d ? w_ih_b : w_ih_f;
    const float* bias = d ? b_b    : b_f;

    __shared__ float As[BK][BM];
    __shared__ float Bs[BK][BN];

    int tid = threadIdx.x;
    int tx = tid & 15, ty = tid >> 4;
    int t0 = blockIdx.y * BM, r0 = blockIdx.x * BN;

    float acc[8][8];
#pragma unroll
    for (int i = 0; i < 8; i++)
#pragma unroll
        for (int j = 0; j < 8; j++) acc[i][j] = 0.f;

    int lm = tid >> 2;            // 0..63
    int lk = (tid & 3) * 4;       // 0,4,8,12

    for (int k0 = 0; k0 < E; k0 += BK) {
#pragma unroll
        for (int rep = 0; rep < 2; rep++) {
            float4 v = *(const float4*)(g_x + (size_t)(t0 + lm + rep * 64) * E + k0 + lk);
            As[lk + 0][lm + rep * 64] = v.x;
            As[lk + 1][lm + rep * 64] = v.y;
            As[lk + 2][lm + rep * 64] = v.z;
            As[lk + 3][lm + rep * 64] = v.w;
            float4 w = *(const float4*)(W + (size_t)(r0 + lm + rep * 64) * E + k0 + lk);
            Bs[lk + 0][lm + rep * 64] = w.x;
            Bs[lk + 1][lm + rep * 64] = w.y;
            Bs[lk + 2][lm + rep * 64] = w.z;
            Bs[lk + 3][lm + rep * 64] = w.w;
        }
        __syncthreads();
#pragma unroll
        for (int k = 0; k < BK; k++) {
            float a[8], b[8];
            *(float4*)(a)     = *(const float4*)&As[k][ty * 8];
            *(float4*)(a + 4) = *(const float4*)&As[k][ty * 8 + 4];
            *(float4*)(b)     = *(const float4*)&Bs[k][tx * 8];
            *(float4*)(b + 4) = *(const float4*)&Bs[k][tx * 8 + 4];
#pragma unroll
            for (int i = 0; i < 8; i++)
#pragma unroll
                for (int j = 0; j < 8; j++) acc[i][j] += a[i] * b[j];
        }
        __syncthreads();
    }

    float* out = g_xg[d];
#pragma unroll
    for (int i = 0; i < 8; i++) {
        int t = t0 + ty * 8 + i;
#pragma unroll
        for (int j = 0; j < 8; j += 4) {
            int r = r0 + tx * 8 + j;
            float4 v = {acc[i][j] + bias[r], acc[i][j + 1] + bias[r + 1],
                        acc[i][j + 2] + bias[r + 2], acc[i][j + 3] + bias[r + 3]};
            *(float4*)(out + (size_t)t * G4 + r) = v;
        }
    }
}

// ---------------- persistent bidirectional LSTM recurrence ----------------
// 128 CTAs x 288 threads. CTA (d*64+b) owns h[8b,8b+8) of direction d.
// Warps 0-7: producers. warp w polls its own 64-col segment of h_prev
// (single v2 volatile load), stages to warp-private smem, packed-f32x2 dot
// with W_hh held in registers as u64 pairs, writes partial, bar.arrive.
// Warp 8: reducer. bar.sync, sums partials, activations, publishes h
// (data-as-flag: canary-poisoned buffer, publish store IS the flag).
__device__ __forceinline__ float sig_f(float x) { return 1.f / (1.f + __expf(-x)); }
__device__ __forceinline__ float tanh_f(float x) { return 1.f - 2.f / (__expf(2.f * x) + 1.f); }

#define FMA2(acc, a, b) asm("fma.rn.f32x2 %0, %1, %2, %0;" : "+l"(acc) : "l"(a), "l"(b))
#define ADD2(acc, b)    asm("add.rn.f32x2 %0, %0, %1;" : "+l"(acc) : "l"(b))

__global__ void __launch_bounds__(288, 1) k_lstm(const float* __restrict__ w_hh_f,
                                                 const float* __restrict__ w_hh_b,
                                                 const float* __restrict__ h0,
                                                 const float* __restrict__ c0) {
    int cta = blockIdx.x;
    int d = cta >> 6;
    int b = cta & 63;
    const float* Whh = d ? w_hh_b : w_hh_f;

    int tid  = threadIdx.x;
    int wid  = tid >> 5;
    int lane = tid & 31;

    __shared__ float sh_h[8][64];       // warp-private staging
    __shared__ float sh_part[8 * 32];   // [seg][gate-row] partials

    float* hout = g_h[d];

    if (wid < 8) {
        // ---------------- producer warp ----------------
        int seg  = wid;
        int gate = lane >> 3, jj = lane & 7;
        int grow = gate * HD + b * 8 + jj;

        // W_hh segment into registers as packed f32 pairs (u64)
        unsigned long long wq[32];
        {
            const ulonglong2* wr = (const ulonglong2*)(Whh + (size_t)grow * HD + seg * 64);
#pragma unroll
            for (int m = 0; m < 16; m++) {
                ulonglong2 v = wr[m];
                wq[2 * m] = v.x; wq[2 * m + 1] = v.y;
            }
        }

        for (int s = 0; s < T; s++) {
            int t = d ? (T - 1 - s) : s;
            float2 hv;
            if (s == 0) {
                hv = *(const float2*)(h0 + d * HD + seg * 64 + lane * 2);
            } else {
                int tp = d ? (t + 1) : (t - 1);
                const float* hp = hout + (size_t)tp * HD + seg * 64 + lane * 2;
                unsigned a, bb;
                do {
                    asm volatile("ld.volatile.global.v2.u32 {%0, %1}, [%2];"
                                 : "=r"(a), "=r"(bb) : "l"(hp));
                } while (a == CANARY || bb == CANARY);
                hv.x = __uint_as_float(a);
                hv.y = __uint_as_float(bb);
            }
            sh_h[seg][lane * 2]     = hv.x;
            sh_h[seg][lane * 2 + 1] = hv.y;
            __syncwarp();

            // packed dot over the 64-col segment
            unsigned long long a0 = 0, a1 = 0, a2 = 0, a3 = 0;
            const ulonglong2* hq = (const ulonglong2*)sh_h[seg];
#pragma unroll
            for (int m = 0; m < 16; m += 2) {
                ulonglong2 h0v = hq[m];
                ulonglong2 h1v = hq[m + 1];
                FMA2(a0, wq[2 * m],     h0v.x);
                FMA2(a1, wq[2 * m + 1], h0v.y);
                FMA2(a2, wq[2 * m + 2], h1v.x);
                FMA2(a3, wq[2 * m + 3], h1v.y);
            }
            ADD2(a0, a2);
            ADD2(a1, a3);
            ADD2(a0, a1);
            float lo = __uint_as_float((unsigned)(a0 & 0xFFFFFFFFull));
            float hi = __uint_as_float((unsigned)(a0 >> 32));
            sh_part[seg * 32 + lane] = lo + hi;
            asm volatile("bar.arrive 1, 288;");
        }
    } else {
        // ---------------- reducer warp ----------------
        int gate = lane >> 3, jj = lane & 7;
        int grow = gate * HD + b * 8 + jj;
        const float* xg = g_xg[d];

        float c = 0.f;
        if (lane < 8) c = c0[d * HD + b * 8 + lane];

        int t0i = d ? (T - 1) : 0;
        float xg_cur = __ldg(xg + (size_t)t0i * G4 + grow);

        for (int s = 0; s < T; s++) {
            int t = d ? (T - 1 - s) : s;
            asm volatile("bar.sync 1, 288;");

            float xg_use = xg_cur;
            if (s + 1 < T) {
                int tn = d ? (t - 1) : (t + 1);
                xg_cur = __ldg(xg + (size_t)tn * G4 + grow);
            }

            float t0a = sh_part[0 * 32 + lane] + sh_part[1 * 32 + lane];
            float t1a = sh_part[2 * 32 + lane] + sh_part[3 * 32 + lane];
            float t2a = sh_part[4 * 32 + lane] + sh_part[5 * 32 + lane];
            float t3a = sh_part[6 * 32 + lane] + sh_part[7 * 32 + lane];
            float tot = xg_use + ((t0a + t1a) + (t2a + t3a));

            unsigned m = 0xFFFFFFFFu;
            float xi  = __shfl_sync(m, tot, (lane & 7));
            float xf  = __shfl_sync(m, tot, 8 + (lane & 7));
            float xgg = __shfl_sync(m, tot, 16 + (lane & 7));
            float xo  = __shfl_sync(m, tot, 24 + (lane & 7));
            if (lane < 8) {
                c = sig_f(xf) * c + sig_f(xi) * tanh_f(xgg);
                float hnew = sig_f(xo) * tanh_f(c);
                asm volatile("st.volatile.global.f32 [%0], %1;"
                             :: "l"(hout + (size_t)t * HD + b * 8 + lane), "f"(hnew));
            }
        }
    }
}

// ---------------- emissions: feats = [hf|hb] @ W_out^T + b_out ----------------
__global__ void k_feats(const float* __restrict__ W_out, const float* __restrict__ b_out) {
    int t = blockIdx.x;
    int tid = threadIdx.x;         // 128
    int tag = tid >> 2, q = tid & 3;
    const float* wrow = W_out + (size_t)tag * 1024 + q * 256;
    const float* hs = (q < 2) ? (g_h[0] + (size_t)t * HD + q * 256)
                              : (g_h[1] + (size_t)t * HD + (q - 2) * 256);
    float sum = 0.f;
#pragma unroll 8
    for (int k = 0; k < 256; k += 4) {
        float4 w4 = *(const float4*)(wrow + k);
        float4 h4 = *(const float4*)(hs + k);
        sum += w4.x * h4.x + w4.y * h4.y + w4.z * h4.z + w4.w * h4.w;
    }
    sum += __shfl_xor_sync(0xFFFFFFFFu, sum, 1);
    sum += __shfl_xor_sync(0xFFFFFFFFu, sum, 2);
    if (q == 0) g_feats[t * TAGS + tag] = sum + b_out[tag];
}

// ---------------- Viterbi (single warp; bp in smem; exact argmax keys) --------
__device__ __forceinline__ unsigned long long vkey(float v, int j) {
    unsigned u = __float_as_uint(v);
    u ^= (u & 0x80000000u) ? 0xFFFFFFFFu : 0x80000000u;   // sortable float
    return (((unsigned long long)u) << 32) | (unsigned)(31 - j); // ties -> lowest j
}
__device__ __forceinline__ unsigned long long umax64(unsigned long long a, unsigned long long b) {
    return a > b ? a : b;
}

extern __shared__ unsigned char vit_smem[];
__global__ void k_viterbi(const float* __restrict__ transitions, float* __restrict__ out,
                          int out_size) {
    unsigned char* bp = vit_smem;                 // T*TAGS bytes
    float* fv = (float*)(vit_smem + T * TAGS);    // TAGS floats
    int n = threadIdx.x;

    float tr[TAGS];
#pragma unroll
    for (int j = 0; j < TAGS; j++) tr[j] = transitions[n * TAGS + j];

    fv[n] = (n == START) ? 0.f : NEGV;
    __syncwarp();

    float f0 = g_feats[0 * TAGS + n];
    float f1 = g_feats[1 * TAGS + n];

    for (int t = 0; t < T; t++) {
        unsigned long long k0 = 0, k1 = 0, k2 = 0, k3 = 0;
#pragma unroll
        for (int j = 0; j < 8; j++) {
            k0 = umax64(k0, vkey(fv[j]      + tr[j],      j));
            k1 = umax64(k1, vkey(fv[j + 8]  + tr[j + 8],  j + 8));
            k2 = umax64(k2, vkey(fv[j + 16] + tr[j + 16], j + 16));
            k3 = umax64(k3, vkey(fv[j + 24] + tr[j + 24], j + 24));
        }
        unsigned long long kmax = umax64(umax64(k0, k1), umax64(k2, k3));
        int arg = 31 - (int)(kmax & 31ull);
        float best = fv[arg] + tr[arg];
        float feat = (t & 1) ? f1 : f0;
        if (t + 2 < T) {
            float nf = g_feats[(t + 2) * TAGS + n];
            if (t & 1) f1 = nf; else f0 = nf;
        }
        float fvn = best + feat;
        bp[t * TAGS + n] = (unsigned char)arg;
        __syncwarp();
        fv[n] = fvn;
        __syncwarp();
    }

    // terminal argmax
    float term = fv[n] + transitions[STOP * TAGS + n];
    unsigned long long key = vkey(term, n);
#pragma unroll
    for (int o = 16; o; o >>= 1) key = umax64(key, __shfl_xor_sync(0xFFFFFFFFu, key, o));
    int best = 31 - (int)(key & 31ull);
    float score = fv[best] + transitions[STOP * TAGS + best];

    if (n == 0) {
        if (out_size >= T + 1) {
            out[0] = score;
            int tag = best;
            for (int t = T - 1; t >= 0; t--) {
                out[1 + t] = (float)tag;
                tag = bp[t * TAGS + tag];
            }
        } else if (out_size >= T) {
            int tag = best;
            for (int t = T - 1; t >= 0; t--) {
                out[t] = (float)tag;
                tag = bp[t * TAGS + tag];
            }
        } else {
            out[0] = score;
        }
    }
}

// ---------------- launch ----------------
extern "C" void kernel_launch(void* const* d_in, const int* in_sizes, int n_in,
                              void* d_out, int out_size) {
    const int*   sentence    = (const int*)d_in[0];
    const float* emb         = (const float*)d_in[1];
    const float* w_ih_f      = (const float*)d_in[2];
    const float* w_hh_f      = (const float*)d_in[3];
    const float* b_f         = (const float*)d_in[4];
    const float* w_ih_b      = (const float*)d_in[5];
    const float* w_hh_b      = (const float*)d_in[6];
    const float* b_b         = (const float*)d_in[7];
    const float* W_out       = (const float*)d_in[8];
    const float* b_out       = (const float*)d_in[9];
    const float* transitions = (const float*)d_in[10];
    const float* h0          = (const float*)d_in[11];
    const float* c0          = (const float*)d_in[12];
    float* out = (float*)d_out;

    k_poison<<<2048, 256>>>();
    k_gather<<<T, 128>>>(sentence, emb);
    k_gemm<<<dim3(16, 16, 2), 256>>>(w_ih_f, b_f, w_ih_b, b_b);
    k_lstm<<<128, 288>>>(w_hh_f, w_hh_b, h0, c0);
    k_feats<<<T, 128>>>(W_out, b_out);

    int vit_smem_bytes = T * TAGS + TAGS * (int)sizeof(float);
    cudaFuncSetAttribute(k_viterbi, cudaFuncAttributeMaxDynamicSharedMemorySize, vit_smem_bytes);
    k_viterbi<<<1, 32, vit_smem_bytes>>>(transitions, out, out_size);
}